// round 11
// baseline (speedup 1.0000x reference)
#include <cuda_runtime.h>

#define BQ 128
#define SQ 512
#define NQ 10
#define NST 1024
#define TPB 256
#define AMPS 4
#define PI_F 3.14159265358979f

typedef unsigned long long u64;

// scratch (no allocations allowed)
__device__ float g_dta[BQ*SQ*NQ];
__device__ float g_C[BQ*SQ*NQ];

__device__ __forceinline__ float2 cmul(float2 a, float2 b){
  return make_float2(a.x*b.x - a.y*b.y, a.x*b.y + a.y*b.x);
}

// ---- packed f32x2 helpers (Blackwell FFMA2 via PTX); carrier = u64 ----------
__device__ __forceinline__ u64 pk2(float x, float y){
  u64 d; asm("mov.b64 %0,{%1,%2};" : "=l"(d) : "f"(x), "f"(y)); return d;
}
__device__ __forceinline__ float2 up2(u64 d){
  float2 f; asm("mov.b64 {%0,%1},%2;" : "=f"(f.x), "=f"(f.y) : "l"(d)); return f;
}
__device__ __forceinline__ u64 fma2d(u64 a, u64 b, u64 c){
  u64 r; asm("fma.rn.f32x2 %0,%1,%2,%3;" : "=l"(r) : "l"(a), "l"(b), "l"(c)); return r;
}
__device__ __forceinline__ u64 mul2d(u64 a, u64 b){
  u64 r; asm("mul.rn.f32x2 %0,%1,%2;" : "=l"(r) : "l"(a), "l"(b)); return r;
}
__device__ __forceinline__ u64 fixPQ(u64 P, u64 Q){
  float2 p = up2(P), q = up2(Q);
  return pk2(p.x - q.y, p.y + q.x);
}

// verified QSVT gather map
__device__ __forceinline__ int gmap(int a){
  int v = a;
  v ^= (v & 1) << 9;
#pragma unroll
  for (int i = 8; i >= 0; --i) v ^= ((v >> (9-i)) & 1) << (8-i);
  return v;
}

// ---------------------------------------------------------------------------
__global__ void prep_kernel(const float* __restrict__ angles,
                            const float* __restrict__ W_x,
                            const float* __restrict__ W_dt,
                            const float* __restrict__ b_dt)
{
  int idx = blockIdx.x*blockDim.x + threadIdx.x;
  if (idx >= BQ*SQ) return;
  float a[NQ];
#pragma unroll
  for (int n=0;n<NQ;n++) a[n] = angles[idx*NQ + n];
  float dtr[5];
#pragma unroll
  for (int r=0;r<5;r++){
    float s = 0.f;
#pragma unroll
    for (int n=0;n<NQ;n++) s += a[n]*W_x[r*NQ+n];
    dtr[r]=s;
  }
#pragma unroll
  for (int k=0;k<NQ;k++){
    float s=0.f;
#pragma unroll
    for (int n=0;n<NQ;n++) s += a[n]*W_x[(15+k)*NQ+n];
    g_C[idx*NQ+k]=s;
  }
#pragma unroll
  for (int n=0;n<NQ;n++){
    float s = b_dt[n];
#pragma unroll
    for (int r=0;r<5;r++) s += dtr[r]*W_dt[n*5+r];
    float sp = fmaxf(s, 0.f) + log1pf(expf(-fabsf(s)));
    g_dta[idx*NQ+n] = tanhf(sp)*PI_F;
  }
}

// dual complex shuffle gate on lane bit q (coeffs loaded once, 8 amps)
__device__ __forceinline__ void shflCp2(u64* v0, u64* v1, const u64* Cq, int q){
  u64 csx=Cq[0], csy=Cq[1], cpx=Cq[2], cpy=Cq[3];
#pragma unroll
  for (int m=0;m<AMPS;m++){
    u64 p = __shfl_xor_sync(0xffffffffu, v0[m], 1<<q);
    u64 P = fma2d(cpx, p, mul2d(csx, v0[m]));
    u64 Q = fma2d(cpy, p, mul2d(csy, v0[m]));
    v0[m] = fixPQ(P, Q);
  }
#pragma unroll
  for (int m=0;m<AMPS;m++){
    u64 p = __shfl_xor_sync(0xffffffffu, v1[m], 1<<q);
    u64 P = fma2d(cpx, p, mul2d(csx, v1[m]));
    u64 Q = fma2d(cpy, p, mul2d(csy, v1[m]));
    v1[m] = fixPQ(P, Q);
  }
}

// real (RY) shuffle gate on lane bit q (per-element coefficients)
__device__ __forceinline__ void shflRp(u64* v, float c, float s, int q, int lane){
  float sp = ((lane >> q) & 1) ? s : -s;
  u64 c2 = pk2(c, c), sp2 = pk2(sp, sp);
#pragma unroll
  for (int m=0;m<AMPS;m++){
    u64 p = __shfl_xor_sync(0xffffffffu, v[m], 1<<q);
    v[m] = fma2d(sp2, p, mul2d(c2, v[m]));
  }
}

// dual complex register gate on m-bit bm
__device__ __forceinline__ void regCp2(u64* v0, u64* v1, const u64* G, int bm){
  u64 g0x=G[0],g0y=G[1],g1x=G[2],g1y=G[3],g2x=G[4],g2y=G[5],g3x=G[6],g3y=G[7];
#pragma unroll
  for (int m=0;m<AMPS;m++){
    if (m & bm) continue;
    int mh = m | bm;
    u64 lo = v0[m], hi = v0[mh];
    u64 P = fma2d(g1x, hi, mul2d(g0x, lo));
    u64 Q = fma2d(g1y, hi, mul2d(g0y, lo));
    v0[m]  = fixPQ(P, Q);
    P = fma2d(g3x, hi, mul2d(g2x, lo));
    Q = fma2d(g3y, hi, mul2d(g2y, lo));
    v0[mh] = fixPQ(P, Q);
    lo = v1[m]; hi = v1[mh];
    P = fma2d(g1x, hi, mul2d(g0x, lo));
    Q = fma2d(g1y, hi, mul2d(g0y, lo));
    v1[m]  = fixPQ(P, Q);
    P = fma2d(g3x, hi, mul2d(g2x, lo));
    Q = fma2d(g3y, hi, mul2d(g2y, lo));
    v1[mh] = fixPQ(P, Q);
  }
}

// real register gate on m-bit bm
__device__ __forceinline__ void regRp(u64* v, float c, float s, int bm){
  u64 c2 = pk2(c,c), s2 = pk2(s,s), ns2 = pk2(-s,-s);
#pragma unroll
  for (int m=0;m<AMPS;m++){
    if (m & bm) continue;
    int mh = m | bm;
    u64 lo = v[m], hi = v[mh];
    v[m]  = fma2d(ns2, hi, mul2d(c2, lo));
    v[mh] = fma2d(c2, hi, mul2d(s2, lo));
  }
}

// ---------------------------------------------------------------------------
// 256 threads, TWO batch elements per CTA, 4 amps/thread each, state packed
// (re,im) per u64. amp a = tid*4+m. bits: [1:0]=m (wires 8,9), [6:2]=lane
// (wires 3..7), [9:7]=warp (wires 0,1,2). pos(a) = (a&3)*256 + (a>>2).
// All static tables, coefficient loads and barriers shared between elements;
// the two independent dependency chains interleave to fill MIO gaps.
// ---------------------------------------------------------------------------
__global__ __launch_bounds__(TPB, 1) void qmamba_main(
    const float* __restrict__ angles,
    const float* __restrict__ poly,
    const float* __restrict__ cparams,
    const float* __restrict__ Dg,
    float* __restrict__ out)
{
  __shared__ u64 bufA0[NST], bufA1[NST], bufB0[NST], bufB1[NST];
  __shared__ float2 Ug[20][4];
  __shared__ u64 Kp[2][8][8][2];     // static cross coeffs, packed
  __shared__ u64 K3p0[8][8], K3p1[8][8]; // per-step RY cross coeffs
  __shared__ u64 Ugp[20][2][4];      // packed shuffle coeffs
  __shared__ u64 Urp[4][8];          // packed reg-gate coeffs (gates 8,9,18,19)
  __shared__ float Slo0[32], Shi0[32], Alo0[32], Ahi0[32];
  __shared__ float Slo1[32], Shi1[32], Alo1[32], Ahi1[32];
  __shared__ float chs0[NQ], shs0[NQ], whs0[NQ], fcs0[NQ], fss0[NQ];
  __shared__ float chs1[NQ], shs1[NQ], whs1[NQ], fcs1[NQ], fss1[NQ];
  __shared__ float pcs[4], Dsh[NQ];
  __shared__ float zred0[8][NQ], zred1[8][NQ];

  const int tid = threadIdx.x;
  const int lane = tid & 31;
  const int warp = tid >> 5;
  const int b0 = 2*blockIdx.x;
  const int b1 = b0 + 1;

  // ---- static setup --------------------------------------------------------
  if (tid < 20) {
    int layer = tid/10, wire = tid%10;
    int k = (layer*NQ + wire)*3;
    float al = cparams[k], be = cparams[k+1], ga = cparams[k+2];
    float sa, ca, sb, cb, sg, cg;
    sincosf(0.5f*al, &sa, &ca);
    sincosf(0.5f*be, &sb, &cb);
    sincosf(0.5f*ga, &sg, &cg);
    float2 m00 = make_float2( cb*ca,  sb*sa);
    float2 m01 = make_float2(-sb*ca, -cb*sa);
    float2 m10 = make_float2( sb*ca, -cb*sa);
    float2 m11 = make_float2( cb*ca, -sb*sa);
    float2 e0 = make_float2(cg, -sg);
    float2 e1 = make_float2(cg,  sg);
    Ug[tid][0] = cmul(e0, m00);
    Ug[tid][1] = cmul(e0, m01);
    Ug[tid][2] = cmul(e1, m10);
    Ug[tid][3] = cmul(e1, m11);
  }
  if (tid < 4) pcs[tid] = poly[tid];
  float pA = 0.f, pC = 0.f;   // per-thread carried scalars (group-dependent)
  if (tid < NQ) {
    Dsh[tid] = Dg[tid];
    int bi = b0*SQ*NQ + tid;
    pA = angles[bi]; pC = g_C[bi];
    float dta = g_dta[bi];
    chs0[tid] = 1.f; shs0[tid] = 0.f;   // h=0 at step 0
    whs0[tid] = dta * (0.5f*PI_F);
    float s_, c_;
    __sincosf(0.5f*pA*dta, &s_, &c_);
    fcs0[tid] = c_; fss0[tid] = s_;
  } else if (tid >= 32 && tid < 32+NQ) {
    int w = tid - 32;
    int bi = b1*SQ*NQ + w;
    pA = angles[bi]; pC = g_C[bi];
    float dta = g_dta[bi];
    chs1[w] = 1.f; shs1[w] = 0.f;
    whs1[w] = dta * (0.5f*PI_F);
    float s_, c_;
    __sincosf(0.5f*pA*dta, &s_, &c_);
    fcs1[w] = c_; fss1[w] = s_;
  }
  __syncthreads();

  // static packed cross coefficients Kp[L][w][d][part]
  {
    int L = tid >> 7;
    int w = (tid >> 4) & 7;
    int d = (tid >> 1) & 7;
    int part = tid & 1;
    int rA=(w>>2)&1, rB=(w>>1)&1, rC=w&1;
    int dA=(d>>2)&1, dB=(d>>1)&1, dC=d&1;
    float2 k = cmul(Ug[L*10+0][rA*2 + (rA^dA)],
               cmul(Ug[L*10+1][rB*2 + (rB^dB)],
                    Ug[L*10+2][rC*2 + (rC^dC)]));
    float val = part ? k.y : k.x;
    Kp[L][w][d][part] = pk2(val, val);
  }
  if (tid < 160) {
    int g = tid >> 3;
    int bt = (tid >> 2) & 1;
    int c = tid & 3;
    float2 cs = bt ? Ug[g][3] : Ug[g][0];
    float2 cp = bt ? Ug[g][2] : Ug[g][1];
    float val = (c==0) ? cs.x : (c==1) ? cs.y : (c==2) ? cp.x : cp.y;
    Ugp[g][bt][c] = pk2(val, val);
  }
  if (tid < 32) {
    int gi = tid >> 3;
    int gate = (gi < 2) ? (8 + gi) : (16 + gi);   // 8,9,18,19
    int c = (tid >> 1) & 3;
    int part = tid & 1;
    float2 gv = Ug[gate][c];
    float val = part ? gv.y : gv.x;
    Urp[gi][2*c+part] = pk2(val, val);
  }

  // per-thread static: QSVT gather powers + fused-gather positions
  int rT1[AMPS], rT2[AMPS], rT3[AMPS], rT4[AMPS], posJ[AMPS];
#pragma unroll
  for (int m=0;m<AMPS;m++){
    int a = tid*AMPS + m;
    rT1[m] = gmap(a);
    rT2[m] = gmap(rT1[m]);
    rT3[m] = gmap(rT2[m]);
    rT4[m] = gmap(rT3[m]);
    int j0 = a ^ (a >> 1);
    posJ[m] = ((j0 & 3) << 8) | (j0 >> 2);
  }
  __syncthreads();

  u64 v0[AMPS], v1[AMPS];

  // ---- sequential scan -----------------------------------------------------
#pragma unroll 1
  for (int s = 0; s < SQ; ++s) {
    // prefetch next-step per-wire inputs (each group for its element)
    float nA=0.f, nD=0.f, nC=0.f;
    if (s+1 < SQ) {
      if (tid < NQ) {
        int bn = (b0*SQ + s + 1)*NQ + tid;
        nA = angles[bn]; nD = g_dta[bn]; nC = g_C[bn];
      } else if (tid >= 32 && tid < 32+NQ) {
        int bn = (b1*SQ + s + 1)*NQ + (tid-32);
        nA = angles[bn]; nD = g_dta[bn]; nC = g_C[bn];
      }
    }
    // per-step split tables: 4 groups of 64 threads
    if (tid < 64) {                       // S/A tables el0
      int j = tid & 31;
      bool hi = tid >= 32;
      float sm = 0.f, am = 1.f;
#pragma unroll
      for (int q=0;q<5;q++){
        int w = hi ? (4-q) : (9-q);
        int bit = (j>>q)&1;
        sm += bit ? whs0[w] : -whs0[w];
        am *= bit ? shs0[w] : chs0[w];
      }
      if (hi){ Shi0[j]=sm; Ahi0[j]=am; } else { Slo0[j]=sm; Alo0[j]=am; }
    } else if (tid < 128) {               // S/A tables el1
      int t2 = tid - 64;
      int j = t2 & 31;
      bool hi = t2 >= 32;
      float sm = 0.f, am = 1.f;
#pragma unroll
      for (int q=0;q<5;q++){
        int w = hi ? (4-q) : (9-q);
        int bit = (j>>q)&1;
        sm += bit ? whs1[w] : -whs1[w];
        am *= bit ? shs1[w] : chs1[w];
      }
      if (hi){ Shi1[j]=sm; Ahi1[j]=am; } else { Slo1[j]=sm; Alo1[j]=am; }
    } else if (tid < 192) {               // K3p el0
      int t = tid - 128;
      int w = t >> 3, d = t & 7;
      float f0 = (d&4) ? ((w&4) ? fss0[0] : -fss0[0]) : fcs0[0];
      float f1 = (d&2) ? ((w&2) ? fss0[1] : -fss0[1]) : fcs0[1];
      float f2 = (d&1) ? ((w&1) ? fss0[2] : -fss0[2]) : fcs0[2];
      float k3 = f0*f1*f2;
      K3p0[w][d] = pk2(k3, k3);
    } else {                              // K3p el1
      int t = tid - 192;
      int w = t >> 3, d = t & 7;
      float f0 = (d&4) ? ((w&4) ? fss1[0] : -fss1[0]) : fcs1[0];
      float f1 = (d&2) ? ((w&2) ? fss1[1] : -fss1[1]) : fcs1[1];
      float f2 = (d&1) ? ((w&1) ? fss1[2] : -fss1[2]) : fcs1[2];
      float k3 = f0*f1*f2;
      K3p1[w][d] = pk2(k3, k3);
    }
    __syncthreads();

    // init in registers: both elements through the entire QSVT block
    {
      float p0=pcs[0], p1=pcs[1], p2=pcs[2], p3=pcs[3];
#pragma unroll
      for (int m=0;m<AMPS;m++){
        float phi = p3*(Shi0[rT1[m]>>5] + Slo0[rT1[m]&31])
                  + p2*(Shi0[rT2[m]>>5] + Slo0[rT2[m]&31])
                  + p1*(Shi0[rT3[m]>>5] + Slo0[rT3[m]&31])
                  + p0*(Shi0[rT4[m]>>5] + Slo0[rT4[m]&31]);
        float am = Ahi0[rT4[m]>>5] * Alo0[rT4[m]&31];
        float sp, cp; __sincosf(phi, &sp, &cp);
        v0[m] = pk2(am*cp, am*sp);
        float phj = p3*(Shi1[rT1[m]>>5] + Slo1[rT1[m]&31])
                  + p2*(Shi1[rT2[m]>>5] + Slo1[rT2[m]&31])
                  + p1*(Shi1[rT3[m]>>5] + Slo1[rT3[m]&31])
                  + p0*(Shi1[rT4[m]>>5] + Slo1[rT4[m]&31]);
        float an = Ahi1[rT4[m]>>5] * Alo1[rT4[m]&31];
        __sincosf(phj, &sp, &cp);
        v1[m] = pk2(an*cp, an*sp);
      }
    }

    // ======== section 1: layer-1 gates ========
#pragma unroll
    for (int m=0;m<AMPS;m++){ bufA0[(m<<8) + tid] = v0[m]; bufA1[(m<<8) + tid] = v1[m]; }
    __syncthreads();
    {
      u64 kx[8], ky[8];
#pragma unroll
      for (int d=0; d<8; d++){ kx[d] = Kp[0][warp][d][0]; ky[d] = Kp[0][warp][d][1]; }
#pragma unroll
      for (int m=0;m<AMPS;m++){
        int p = (m<<8) + tid;
        u64 w0 = bufA0[p], w1 = bufA1[p];
        u64 P0 = mul2d(kx[0], w0), Q0 = mul2d(ky[0], w0);
        u64 P1 = mul2d(kx[0], w1), Q1 = mul2d(ky[0], w1);
#pragma unroll
        for (int d=1; d<8; d++){
          u64 wd0 = bufA0[p ^ (d<<5)], wd1 = bufA1[p ^ (d<<5)];
          P0 = fma2d(kx[d], wd0, P0); Q0 = fma2d(ky[d], wd0, Q0);
          P1 = fma2d(kx[d], wd1, P1); Q1 = fma2d(ky[d], wd1, Q1);
        }
        v0[m] = fixPQ(P0, Q0);
        v1[m] = fixPQ(P1, Q1);
      }
    }
    shflCp2(v0, v1, Ugp[3][(lane>>4)&1], 4);
    shflCp2(v0, v1, Ugp[4][(lane>>3)&1], 3);
    shflCp2(v0, v1, Ugp[5][(lane>>2)&1], 2);
    shflCp2(v0, v1, Ugp[6][(lane>>1)&1], 1);
    shflCp2(v0, v1, Ugp[7][lane&1], 0);
    regCp2(v0, v1, Urp[0], 2);
    regCp2(v0, v1, Urp[1], 1);

    // ======== section 2: chain gather fused with layer-2 cross gate ========
#pragma unroll
    for (int m=0;m<AMPS;m++){ bufB0[(m<<8) + tid] = v0[m]; bufB1[(m<<8) + tid] = v1[m]; }
    __syncthreads();
    {
      u64 kx[8], ky[8];
#pragma unroll
      for (int d=0; d<8; d++){ kx[d] = Kp[1][warp][d][0]; ky[d] = Kp[1][warp][d][1]; }
#pragma unroll
      for (int m=0;m<AMPS;m++){
        int p = posJ[m];
        u64 w0 = bufB0[p], w1 = bufB1[p];
        u64 P0 = mul2d(kx[0], w0), Q0 = mul2d(ky[0], w0);
        u64 P1 = mul2d(kx[0], w1), Q1 = mul2d(ky[0], w1);
#pragma unroll
        for (int d=1; d<8; d++){
          int pd = p ^ ((d<<5) ^ (d<<4));
          u64 wd0 = bufB0[pd], wd1 = bufB1[pd];
          P0 = fma2d(kx[d], wd0, P0); Q0 = fma2d(ky[d], wd0, Q0);
          P1 = fma2d(kx[d], wd1, P1); Q1 = fma2d(ky[d], wd1, Q1);
        }
        v0[m] = fixPQ(P0, Q0);
        v1[m] = fixPQ(P1, Q1);
      }
    }
    shflCp2(v0, v1, Ugp[13][(lane>>4)&1], 4);
    shflCp2(v0, v1, Ugp[14][(lane>>3)&1], 3);
    shflCp2(v0, v1, Ugp[15][(lane>>2)&1], 2);
    shflCp2(v0, v1, Ugp[16][(lane>>1)&1], 1);
    shflCp2(v0, v1, Ugp[17][lane&1], 0);
    regCp2(v0, v1, Urp[2], 2);
    regCp2(v0, v1, Urp[3], 1);

    // ======== section 3: chain gather fused with final-RY cross gate ========
#pragma unroll
    for (int m=0;m<AMPS;m++){ bufA0[(m<<8) + tid] = v0[m]; bufA1[(m<<8) + tid] = v1[m]; }
    __syncthreads();
    {
      u64 k30[8], k31[8];
#pragma unroll
      for (int d=0; d<8; d++){ k30[d] = K3p0[warp][d]; k31[d] = K3p1[warp][d]; }
#pragma unroll
      for (int m=0;m<AMPS;m++){
        int p = posJ[m];
        u64 acc0 = mul2d(k30[0], bufA0[p]);
        u64 acc1 = mul2d(k31[0], bufA1[p]);
#pragma unroll
        for (int d=1; d<8; d++){
          int pd = p ^ ((d<<5) ^ (d<<4));
          acc0 = fma2d(k30[d], bufA0[pd], acc0);
          acc1 = fma2d(k31[d], bufA1[pd], acc1);
        }
        v0[m] = acc0;
        v1[m] = acc1;
      }
    }
    shflRp(v0, fcs0[3], fss0[3], 4, lane);
    shflRp(v1, fcs1[3], fss1[3], 4, lane);
    shflRp(v0, fcs0[4], fss0[4], 3, lane);
    shflRp(v1, fcs1[4], fss1[4], 3, lane);
    shflRp(v0, fcs0[5], fss0[5], 2, lane);
    shflRp(v1, fcs1[5], fss1[5], 2, lane);
    shflRp(v0, fcs0[6], fss0[6], 1, lane);
    shflRp(v1, fcs1[6], fss1[6], 1, lane);
    shflRp(v0, fcs0[7], fss0[7], 0, lane);
    shflRp(v1, fcs1[7], fss1[7], 0, lane);
    regRp(v0, fcs0[8], fss0[8], 2);
    regRp(v1, fcs1[8], fss1[8], 2);
    regRp(v0, fcs0[9], fss0[9], 1);
    regRp(v1, fcs1[9], fss1[9], 1);

    // ======== measurement (both elements) ========
    float S0=0.f, SbH0=0.f, SbL0=0.f, S1=0.f, SbH1=0.f, SbL1=0.f;
#pragma unroll
    for (int m=0;m<AMPS;m++){
      float2 f = up2(v0[m]);
      float pm = f.x*f.x + f.y*f.y;
      S0 += pm;
      if (m & 2) SbH0 += pm;
      if (m & 1) SbL0 += pm;
      float2 g = up2(v1[m]);
      float pn = g.x*g.x + g.y*g.y;
      S1 += pn;
      if (m & 2) SbH1 += pn;
      if (m & 1) SbL1 += pn;
    }
#pragma unroll
    for (int off=16; off>0; off>>=1){
      SbH0 += __shfl_xor_sync(0xffffffffu, SbH0, off);
      SbL0 += __shfl_xor_sync(0xffffffffu, SbL0, off);
      SbH1 += __shfl_xor_sync(0xffffffffu, SbH1, off);
      SbL1 += __shfl_xor_sync(0xffffffffu, SbL1, off);
    }
    // Walsh-Hadamard on S over 5 lane bits (both elements)
#pragma unroll
    for (int q=16; q>0; q>>=1){
      float t0 = __shfl_xor_sync(0xffffffffu, S0, q);
      float t1 = __shfl_xor_sync(0xffffffffu, S1, q);
      S0 = ((lane & q) ? (t0 - S0) : (S0 + t0));
      S1 = ((lane & q) ? (t1 - S1) : (S1 + t1));
    }
    if (lane == 0){
      zred0[warp][0] = (warp&4) ? -S0 : S0;
      zred0[warp][1] = (warp&2) ? -S0 : S0;
      zred0[warp][2] = (warp&1) ? -S0 : S0;
      zred0[warp][8] = S0 - 2.f*SbH0;
      zred0[warp][9] = S0 - 2.f*SbL0;
      zred1[warp][0] = (warp&4) ? -S1 : S1;
      zred1[warp][1] = (warp&2) ? -S1 : S1;
      zred1[warp][2] = (warp&1) ? -S1 : S1;
      zred1[warp][8] = S1 - 2.f*SbH1;
      zred1[warp][9] = S1 - 2.f*SbL1;
    } else if (lane == 16){ zred0[warp][3] = S0; zred1[warp][3] = S1; }
    else if (lane == 8) { zred0[warp][4] = S0; zred1[warp][4] = S1; }
    else if (lane == 4) { zred0[warp][5] = S0; zred1[warp][5] = S1; }
    else if (lane == 2) { zred0[warp][6] = S0; zred1[warp][6] = S1; }
    else if (lane == 1) { zred0[warp][7] = S0; zred1[warp][7] = S1; }
    __syncthreads();

    // ======== h update / output (two groups, parallel warps) ========
    if (tid < NQ){
      float hn = zred0[0][tid] + zred0[1][tid] + zred0[2][tid] + zred0[3][tid]
               + zred0[4][tid] + zred0[5][tid] + zred0[6][tid] + zred0[7][tid];
      int bi = (b0*SQ + s)*NQ + tid;
      out[bi] = pC*hn + Dsh[tid]*pA;
      if (s+1 < SQ){
        float s_, c_;
        __sincosf(0.5f*hn, &s_, &c_);
        chs0[tid] = c_; shs0[tid] = s_;
        whs0[tid] = nD * (0.5f*PI_F);
        __sincosf(0.5f*nA*nD, &s_, &c_);
        fcs0[tid] = c_; fss0[tid] = s_;
        pA = nA; pC = nC;
      }
    } else if (tid >= 32 && tid < 32+NQ){
      int w = tid - 32;
      float hn = zred1[0][w] + zred1[1][w] + zred1[2][w] + zred1[3][w]
               + zred1[4][w] + zred1[5][w] + zred1[6][w] + zred1[7][w];
      int bi = (b1*SQ + s)*NQ + w;
      out[bi] = pC*hn + Dsh[w]*pA;
      if (s+1 < SQ){
        float s_, c_;
        __sincosf(0.5f*hn, &s_, &c_);
        chs1[w] = c_; shs1[w] = s_;
        whs1[w] = nD * (0.5f*PI_F);
        __sincosf(0.5f*nA*nD, &s_, &c_);
        fcs1[w] = c_; fss1[w] = s_;
        pA = nA; pC = nC;
      }
    }
    __syncthreads();
  }
}

// ---------------------------------------------------------------------------
extern "C" void kernel_launch(void* const* d_in, const int* in_sizes, int n_in,
                              void* d_out, int out_size)
{
  const float* angles  = (const float*)d_in[0];
  const float* W_x     = (const float*)d_in[1];
  const float* W_dt    = (const float*)d_in[2];
  const float* b_dt    = (const float*)d_in[3];
  const float* poly    = (const float*)d_in[4];
  const float* cparams = (const float*)d_in[5];
  const float* D       = (const float*)d_in[6];
  float* out = (float*)d_out;

  prep_kernel<<<(BQ*SQ + 255)/256, 256>>>(angles, W_x, W_dt, b_dt);
  qmamba_main<<<BQ/2, TPB>>>(angles, poly, cparams, D, out);
}

// round 12
// speedup vs baseline: 1.9439x; 1.9439x over previous
#include <cuda_runtime.h>

#define BQ 128
#define SQ 512
#define NQ 10
#define NST 1024
#define TPB 256
#define AMPS 4
#define PI_F 3.14159265358979f

typedef unsigned long long u64;

// scratch (no allocations allowed)
__device__ float g_dta[BQ*SQ*NQ];
__device__ float g_C[BQ*SQ*NQ];

__device__ __forceinline__ float2 cmul(float2 a, float2 b){
  return make_float2(a.x*b.x - a.y*b.y, a.x*b.y + a.y*b.x);
}

// ---- packed f32x2 helpers (Blackwell FFMA2 via PTX); carrier = u64 ----------
__device__ __forceinline__ u64 pk2(float x, float y){
  u64 d; asm("mov.b64 %0,{%1,%2};" : "=l"(d) : "f"(x), "f"(y)); return d;
}
__device__ __forceinline__ float2 up2(u64 d){
  float2 f; asm("mov.b64 {%0,%1},%2;" : "=f"(f.x), "=f"(f.y) : "l"(d)); return f;
}
__device__ __forceinline__ u64 fma2d(u64 a, u64 b, u64 c){
  u64 r; asm("fma.rn.f32x2 %0,%1,%2,%3;" : "=l"(r) : "l"(a), "l"(b), "l"(c)); return r;
}
__device__ __forceinline__ u64 mul2d(u64 a, u64 b){
  u64 r; asm("mul.rn.f32x2 %0,%1,%2;" : "=l"(r) : "l"(a), "l"(b)); return r;
}
__device__ __forceinline__ u64 fixPQ(u64 P, u64 Q){
  float2 p = up2(P), q = up2(Q);
  return pk2(p.x - q.y, p.y + q.x);
}

// verified QSVT gather map
__device__ __forceinline__ int gmap(int a){
  int v = a;
  v ^= (v & 1) << 9;
#pragma unroll
  for (int i = 8; i >= 0; --i) v ^= ((v >> (9-i)) & 1) << (8-i);
  return v;
}

// bit transpose: swap amp bits 9<->1, 8<->0, 7<->2 (involution)
__device__ __forceinline__ int bswap(int x){
  int keep = x & 0x78;                       // bits 6..3
  int b9=(x>>9)&1, b8=(x>>8)&1, b7=(x>>7)&1;
  int b2=(x>>2)&1, b1=(x>>1)&1, b0=x&1;
  return keep | (b1<<9) | (b0<<8) | (b2<<7) | (b7<<2) | (b9<<1) | b8;
}
// inverse of chain gather g(x)=x^(x>>1): x_p = XOR of j bits 9..p
__device__ __forceinline__ int grayinv(int j){
  int x = 0, c = 0;
#pragma unroll
  for (int p = 9; p >= 0; --p){ c ^= (j>>p)&1; x |= c<<p; }
  return x;
}

// ---------------------------------------------------------------------------
__global__ void prep_kernel(const float* __restrict__ angles,
                            const float* __restrict__ W_x,
                            const float* __restrict__ W_dt,
                            const float* __restrict__ b_dt)
{
  int idx = blockIdx.x*blockDim.x + threadIdx.x;
  if (idx >= BQ*SQ) return;
  float a[NQ];
#pragma unroll
  for (int n=0;n<NQ;n++) a[n] = angles[idx*NQ + n];
  float dtr[5];
#pragma unroll
  for (int r=0;r<5;r++){
    float s = 0.f;
#pragma unroll
    for (int n=0;n<NQ;n++) s += a[n]*W_x[r*NQ+n];
    dtr[r]=s;
  }
#pragma unroll
  for (int k=0;k<NQ;k++){
    float s=0.f;
#pragma unroll
    for (int n=0;n<NQ;n++) s += a[n]*W_x[(15+k)*NQ+n];
    g_C[idx*NQ+k]=s;
  }
#pragma unroll
  for (int n=0;n<NQ;n++){
    float s = b_dt[n];
#pragma unroll
    for (int r=0;r<5;r++) s += dtr[r]*W_dt[n*5+r];
    float sp = fmaxf(s, 0.f) + log1pf(expf(-fabsf(s)));
    g_dta[idx*NQ+n] = tanhf(sp)*PI_F;
  }
}

// complex shuffle gate on lane bit q
__device__ __forceinline__ void shflCp(u64* v, const u64* Cq, int q){
  u64 csx=Cq[0], csy=Cq[1], cpx=Cq[2], cpy=Cq[3];
#pragma unroll
  for (int m=0;m<AMPS;m++){
    u64 p = __shfl_xor_sync(0xffffffffu, v[m], 1<<q);
    u64 P = fma2d(cpx, p, mul2d(csx, v[m]));
    u64 Q = fma2d(cpy, p, mul2d(csy, v[m]));
    v[m] = fixPQ(P, Q);
  }
}

// real (RY) shuffle gate on lane bit q
__device__ __forceinline__ void shflRp(u64* v, float c, float s, int q, int lane){
  float sp = ((lane >> q) & 1) ? s : -s;
  u64 c2 = pk2(c, c), sp2 = pk2(sp, sp);
#pragma unroll
  for (int m=0;m<AMPS;m++){
    u64 p = __shfl_xor_sync(0xffffffffu, v[m], 1<<q);
    v[m] = fma2d(sp2, p, mul2d(c2, v[m]));
  }
}

// complex register gate on m-bit bm
__device__ __forceinline__ void regCp(u64* v, const u64* G, int bm){
  u64 g0x=G[0],g0y=G[1],g1x=G[2],g1y=G[3],g2x=G[4],g2y=G[5],g3x=G[6],g3y=G[7];
#pragma unroll
  for (int m=0;m<AMPS;m++){
    if (m & bm) continue;
    int mh = m | bm;
    u64 lo = v[m], hi = v[mh];
    u64 P = fma2d(g1x, hi, mul2d(g0x, lo));
    u64 Q = fma2d(g1y, hi, mul2d(g0y, lo));
    v[m]  = fixPQ(P, Q);
    P = fma2d(g3x, hi, mul2d(g2x, lo));
    Q = fma2d(g3y, hi, mul2d(g2y, lo));
    v[mh] = fixPQ(P, Q);
  }
}

// real register gate on m-bit bm
__device__ __forceinline__ void regRp(u64* v, float c, float s, int bm){
  u64 c2 = pk2(c,c), s2 = pk2(s,s), ns2 = pk2(-s,-s);
#pragma unroll
  for (int m=0;m<AMPS;m++){
    if (m & bm) continue;
    int mh = m | bm;
    u64 lo = v[m], hi = v[mh];
    v[m]  = fma2d(ns2, hi, mul2d(c2, lo));
    v[mh] = fma2d(c2, hi, mul2d(s2, lo));
  }
}

// ---------------------------------------------------------------------------
// 256 threads, 4 amps/thread, state packed (re,im) per u64.
// L0 layout: amp a = tid*4+m; bits [1:0]=m (wires 8,9), [6:2]=lane (wires 3..7),
// [9:7]=warp (wires 0,1,2). L1 layout = bitswap(9<->1, 8<->0, 7<->2): warp
// wires land on (m1, m0, lane0). Cross-wire gates become 2 reg + 1 shfl after a
// transpose exchange; chain gathers are fused into the exchange's store
// addresses. Every amp crosses shared once per exchange (5/step).
// ---------------------------------------------------------------------------
__global__ __launch_bounds__(TPB, 1) void qmamba_main(
    const float* __restrict__ angles,
    const float* __restrict__ poly,
    const float* __restrict__ cparams,
    const float* __restrict__ Dg,
    float* __restrict__ out)
{
  __shared__ u64 bufA[NST], bufB[NST];
  __shared__ float2 Ug[20][4];
  __shared__ u64 Ugp[20][2][4];      // packed shuffle coeffs
  __shared__ u64 Urp[8][8];          // packed reg coeffs {0,1,8,9,10,11,18,19}
  __shared__ float Slo[32], Shi[32], Alo[32], Ahi[32];
  __shared__ float chs[NQ], shs[NQ], whs[NQ], fcs[NQ], fss[NQ];
  __shared__ float pcs[4], Dsh[NQ];
  __shared__ float zred[8][NQ];

  const int tid = threadIdx.x;
  const int lane = tid & 31;
  const int warp = tid >> 5;
  const int b = blockIdx.x;

  // ---- setup ---------------------------------------------------------------
  if (tid < 20) {
    int layer = tid/10, wire = tid%10;
    int k = (layer*NQ + wire)*3;
    float al = cparams[k], be = cparams[k+1], ga = cparams[k+2];
    float sa, ca, sb, cb, sg, cg;
    sincosf(0.5f*al, &sa, &ca);
    sincosf(0.5f*be, &sb, &cb);
    sincosf(0.5f*ga, &sg, &cg);
    float2 m00 = make_float2( cb*ca,  sb*sa);
    float2 m01 = make_float2(-sb*ca, -cb*sa);
    float2 m10 = make_float2( sb*ca, -cb*sa);
    float2 m11 = make_float2( cb*ca, -sb*sa);
    float2 e0 = make_float2(cg, -sg);
    float2 e1 = make_float2(cg,  sg);
    Ug[tid][0] = cmul(e0, m00);
    Ug[tid][1] = cmul(e0, m01);
    Ug[tid][2] = cmul(e1, m10);
    Ug[tid][3] = cmul(e1, m11);
  }
  if (tid < 4) pcs[tid] = poly[tid];
  float pA = 0.f, pC = 0.f;
  if (tid < NQ) {
    Dsh[tid] = Dg[tid];
    int bi = b*SQ*NQ + tid;
    pA = angles[bi]; pC = g_C[bi];
    float dta = g_dta[bi];
    chs[tid] = 1.f; shs[tid] = 0.f;     // h=0 at step 0
    whs[tid] = dta * (0.5f*PI_F);
    float s_, c_;
    __sincosf(0.5f*pA*dta, &s_, &c_);
    fcs[tid] = c_; fss[tid] = s_;
  }
  __syncthreads();

  // static packed shuffle-gate coefficients Ugp[g][bt][c]
  if (tid < 160) {
    int g = tid >> 3;
    int bt = (tid >> 2) & 1;
    int c = tid & 3;
    float2 cs = bt ? Ug[g][3] : Ug[g][0];
    float2 cp = bt ? Ug[g][2] : Ug[g][1];
    float val = (c==0) ? cs.x : (c==1) ? cs.y : (c==2) ? cp.x : cp.y;
    Ugp[g][bt][c] = pk2(val, val);
  }
  // static packed reg-gate coefficients for gates {0,1,8,9,10,11,18,19}
  if (tid < 64) {
    const int glist[8] = {0,1,8,9,10,11,18,19};
    int gi = tid >> 3;
    int c = (tid >> 1) & 3;
    int part = tid & 1;
    float2 gv = Ug[glist[gi]][c];
    float val = part ? gv.y : gv.x;
    Urp[gi][2*c+part] = pk2(val, val);
  }

  // per-thread static: QSVT gather powers + exchange index sets
  int rT1[AMPS], rT2[AMPS], rT3[AMPS], rT4[AMPS];
  int dstT[AMPS], dstG[AMPS];
#pragma unroll
  for (int m=0;m<AMPS;m++){
    int a = tid*AMPS + m;
    rT1[m] = gmap(a);
    rT2[m] = gmap(rT1[m]);
    rT3[m] = gmap(rT2[m]);
    rT4[m] = gmap(rT3[m]);
    // T-store: amp a (L0) -> its L1 slot, swizzled
    int xp = bswap(a);
    int t1 = xp >> 2;
    dstT[m] = ((xp & 3) << 8) | (t1 ^ ((t1 >> 5) & 1));
    // G-store: own L1 amp j=bswap(a); scatter to L0 slot of x=g^{-1}(j)
    int xg = grayinv(xp);
    int tg = xg >> 2;
    dstG[m] = ((xg & 3) << 8) | (tg ^ ((tg >> 5) & 1));
  }
  const int ldb = tid ^ ((tid >> 5) & 1);   // own-slot swizzled load base
  __syncthreads();

  u64 v[AMPS];

  // ---- sequential scan -----------------------------------------------------
#pragma unroll 1
  for (int s = 0; s < SQ; ++s) {
    // prefetch next-step per-wire inputs
    float nA=0.f, nD=0.f, nC=0.f;
    if (tid < NQ && s+1 < SQ) {
      int bn = (b*SQ + s + 1)*NQ + tid;
      nA = angles[bn]; nD = g_dta[bn]; nC = g_C[bn];
    }
    // per-step split tables over 5-bit halves
    if (tid < 64) {
      int j = tid & 31;
      bool hi = tid >= 32;
      float sm = 0.f, am = 1.f;
#pragma unroll
      for (int q=0;q<5;q++){
        int w = hi ? (4-q) : (9-q);
        int bit = (j>>q)&1;
        sm += bit ? whs[w] : -whs[w];
        am *= bit ? shs[w] : chs[w];
      }
      if (hi){ Shi[j]=sm; Ahi[j]=am; } else { Slo[j]=sm; Alo[j]=am; }
    }
    __syncthreads();

    // init in registers (L0): product state advanced through entire QSVT block
    {
      float p0=pcs[0], p1=pcs[1], p2=pcs[2], p3=pcs[3];
#pragma unroll
      for (int m=0;m<AMPS;m++){
        float phi = p3*(Shi[rT1[m]>>5] + Slo[rT1[m]&31])
                  + p2*(Shi[rT2[m]>>5] + Slo[rT2[m]&31])
                  + p1*(Shi[rT3[m]>>5] + Slo[rT3[m]&31])
                  + p0*(Shi[rT4[m]>>5] + Slo[rT4[m]&31]);
        float am = Ahi[rT4[m]>>5] * Alo[rT4[m]&31];
        float sp, cp; __sincosf(phi, &sp, &cp);
        v[m] = pk2(am*cp, am*sp);
      }
    }

    // ==== phase A (L0): layer-1 wires 3..7 (shfl), 8,9 (reg) ====
    shflCp(v, Ugp[3][(lane>>4)&1], 4);
    shflCp(v, Ugp[4][(lane>>3)&1], 3);
    shflCp(v, Ugp[5][(lane>>2)&1], 2);
    shflCp(v, Ugp[6][(lane>>1)&1], 1);
    shflCp(v, Ugp[7][lane&1], 0);
    regCp(v, Urp[2], 2);   // gate 8
    regCp(v, Urp[3], 1);   // gate 9
    // T1: L0 -> L1
#pragma unroll
    for (int m=0;m<AMPS;m++) bufA[dstT[m]] = v[m];
    __syncthreads();
#pragma unroll
    for (int m=0;m<AMPS;m++) v[m] = bufA[(m<<8) | ldb];
    // ==== phase B (L1): layer-1 wires 0 (m1), 1 (m0), 2 (lane0) ====
    regCp(v, Urp[0], 2);   // gate 0
    regCp(v, Urp[1], 1);   // gate 1
    shflCp(v, Ugp[2][lane&1], 0);
    // G1: chain gather + back to L0
#pragma unroll
    for (int m=0;m<AMPS;m++) bufB[dstG[m]] = v[m];
    __syncthreads();
#pragma unroll
    for (int m=0;m<AMPS;m++) v[m] = bufB[(m<<8) | ldb];

    // ==== phase C (L0): layer-2 wires 3..7, 8,9 ====
    shflCp(v, Ugp[13][(lane>>4)&1], 4);
    shflCp(v, Ugp[14][(lane>>3)&1], 3);
    shflCp(v, Ugp[15][(lane>>2)&1], 2);
    shflCp(v, Ugp[16][(lane>>1)&1], 1);
    shflCp(v, Ugp[17][lane&1], 0);
    regCp(v, Urp[6], 2);   // gate 18
    regCp(v, Urp[7], 1);   // gate 19
    // T2: L0 -> L1
#pragma unroll
    for (int m=0;m<AMPS;m++) bufA[dstT[m]] = v[m];
    __syncthreads();
#pragma unroll
    for (int m=0;m<AMPS;m++) v[m] = bufA[(m<<8) | ldb];
    // ==== phase D (L1): layer-2 wires 0,1,2 ====
    regCp(v, Urp[4], 2);   // gate 10
    regCp(v, Urp[5], 1);   // gate 11
    shflCp(v, Ugp[12][lane&1], 0);
    // G2: chain gather + back to L0
#pragma unroll
    for (int m=0;m<AMPS;m++) bufB[dstG[m]] = v[m];
    __syncthreads();
#pragma unroll
    for (int m=0;m<AMPS;m++) v[m] = bufB[(m<<8) | ldb];

    // ==== phase E (L0): final RY wires 3..7, 8,9 ====
    shflRp(v, fcs[3], fss[3], 4, lane);
    shflRp(v, fcs[4], fss[4], 3, lane);
    shflRp(v, fcs[5], fss[5], 2, lane);
    shflRp(v, fcs[6], fss[6], 1, lane);
    shflRp(v, fcs[7], fss[7], 0, lane);
    regRp(v, fcs[8], fss[8], 2);
    regRp(v, fcs[9], fss[9], 1);
    // T3: L0 -> L1
#pragma unroll
    for (int m=0;m<AMPS;m++) bufA[dstT[m]] = v[m];
    __syncthreads();
#pragma unroll
    for (int m=0;m<AMPS;m++) v[m] = bufA[(m<<8) | ldb];
    // ==== phase F (L1): final RY wires 0,1,2 ====
    regRp(v, fcs[0], fss[0], 2);
    regRp(v, fcs[1], fss[1], 1);
    shflRp(v, fcs[2], fss[2], 0, lane);

    // ======== measurement (L1 layout) ========
    // L1 amp bits: [1:0]=wires 0,1; [2]=wire2; [6:3]=wires 6..3; [9:7]=wires 8,9,7
    float S=0.f, SbH=0.f, SbL=0.f;
#pragma unroll
    for (int m=0;m<AMPS;m++){
      float2 f = up2(v[m]);
      float pm = f.x*f.x + f.y*f.y;
      S += pm;
      if (m & 2) SbH += pm;   // wire 0
      if (m & 1) SbL += pm;   // wire 1
    }
#pragma unroll
    for (int off=16; off>0; off>>=1){
      SbH += __shfl_xor_sync(0xffffffffu, SbH, off);
      SbL += __shfl_xor_sync(0xffffffffu, SbL, off);
    }
    // Walsh-Hadamard on S over 5 lane bits
#pragma unroll
    for (int q=16; q>0; q>>=1){
      float t = __shfl_xor_sync(0xffffffffu, S, q);
      S = ((lane & q) ? (t - S) : (S + t));
    }
    if (lane == 0){
      zred[warp][8] = (warp&4) ? -S : S;   // amp bit9 = wire 8
      zred[warp][9] = (warp&2) ? -S : S;   // amp bit8 = wire 9
      zred[warp][7] = (warp&1) ? -S : S;   // amp bit7 = wire 7
      zred[warp][0] = S - 2.f*SbH;         // wire 0
      zred[warp][1] = S - 2.f*SbL;         // wire 1
    } else if (lane == 16) zred[warp][3] = S;  // amp bit6 = wire 3
    else if (lane == 8)  zred[warp][4] = S;    // wire 4
    else if (lane == 4)  zred[warp][5] = S;    // wire 5
    else if (lane == 2)  zred[warp][6] = S;    // wire 6
    else if (lane == 1)  zred[warp][2] = S;    // amp bit2 = wire 2
    __syncthreads();

    if (tid < NQ){
      float hn = zred[0][tid] + zred[1][tid] + zred[2][tid] + zred[3][tid]
               + zred[4][tid] + zred[5][tid] + zred[6][tid] + zred[7][tid];
      int bi = (b*SQ + s)*NQ + tid;
      out[bi] = pC*hn + Dsh[tid]*pA;
      if (s+1 < SQ){
        float s_, c_;
        __sincosf(0.5f*hn, &s_, &c_);
        chs[tid] = c_; shs[tid] = s_;
        whs[tid] = nD * (0.5f*PI_F);
        __sincosf(0.5f*nA*nD, &s_, &c_);
        fcs[tid] = c_; fss[tid] = s_;
        pA = nA; pC = nC;
      }
    }
    __syncthreads();
  }
}

// ---------------------------------------------------------------------------
extern "C" void kernel_launch(void* const* d_in, const int* in_sizes, int n_in,
                              void* d_out, int out_size)
{
  const float* angles  = (const float*)d_in[0];
  const float* W_x     = (const float*)d_in[1];
  const float* W_dt    = (const float*)d_in[2];
  const float* b_dt    = (const float*)d_in[3];
  const float* poly    = (const float*)d_in[4];
  const float* cparams = (const float*)d_in[5];
  const float* D       = (const float*)d_in[6];
  float* out = (float*)d_out;

  prep_kernel<<<(BQ*SQ + 255)/256, 256>>>(angles, W_x, W_dt, b_dt);
  qmamba_main<<<BQ, TPB>>>(angles, poly, cparams, D, out);
}

// round 13
// speedup vs baseline: 1.9817x; 1.0194x over previous
#include <cuda_runtime.h>

#define BQ 128
#define SQ 512
#define NQ 10
#define NST 1024
#define TPB 256
#define AMPS 4
#define PI_F 3.14159265358979f

typedef unsigned long long u64;

// scratch (no allocations allowed)
__device__ float g_dta[BQ*SQ*NQ];
__device__ float g_C[BQ*SQ*NQ];

__device__ __forceinline__ float2 cmul(float2 a, float2 b){
  return make_float2(a.x*b.x - a.y*b.y, a.x*b.y + a.y*b.x);
}

// ---- packed f32x2 helpers (Blackwell FFMA2 via PTX); carrier = u64 ----------
__device__ __forceinline__ u64 pk2(float x, float y){
  u64 d; asm("mov.b64 %0,{%1,%2};" : "=l"(d) : "f"(x), "f"(y)); return d;
}
__device__ __forceinline__ float2 up2(u64 d){
  float2 f; asm("mov.b64 {%0,%1},%2;" : "=f"(f.x), "=f"(f.y) : "l"(d)); return f;
}
__device__ __forceinline__ u64 fma2d(u64 a, u64 b, u64 c){
  u64 r; asm("fma.rn.f32x2 %0,%1,%2,%3;" : "=l"(r) : "l"(a), "l"(b), "l"(c)); return r;
}
__device__ __forceinline__ u64 mul2d(u64 a, u64 b){
  u64 r; asm("mul.rn.f32x2 %0,%1,%2;" : "=l"(r) : "l"(a), "l"(b)); return r;
}
__device__ __forceinline__ u64 fixPQ(u64 P, u64 Q){
  float2 p = up2(P), q = up2(Q);
  return pk2(p.x - q.y, p.y + q.x);
}

// verified QSVT gather map
__device__ __forceinline__ int gmap(int a){
  int v = a;
  v ^= (v & 1) << 9;
#pragma unroll
  for (int i = 8; i >= 0; --i) v ^= ((v >> (9-i)) & 1) << (8-i);
  return v;
}

// bit transpose: swap amp bits 9<->1, 8<->0, 7<->2 (involution)
__device__ __forceinline__ int bswap(int x){
  int keep = x & 0x78;                       // bits 6..3
  int b9=(x>>9)&1, b8=(x>>8)&1, b7=(x>>7)&1;
  int b2=(x>>2)&1, b1=(x>>1)&1, b0=x&1;
  return keep | (b1<<9) | (b0<<8) | (b2<<7) | (b7<<2) | (b9<<1) | b8;
}
// inverse of chain gather g(x)=x^(x>>1): x_p = XOR of j bits 9..p
__device__ __forceinline__ int grayinv(int j){
  int x = 0, c = 0;
#pragma unroll
  for (int p = 9; p >= 0; --p){ c ^= (j>>p)&1; x |= c<<p; }
  return x;
}

// ---------------------------------------------------------------------------
__global__ void prep_kernel(const float* __restrict__ angles,
                            const float* __restrict__ W_x,
                            const float* __restrict__ W_dt,
                            const float* __restrict__ b_dt)
{
  int idx = blockIdx.x*blockDim.x + threadIdx.x;
  if (idx >= BQ*SQ) return;
  float a[NQ];
#pragma unroll
  for (int n=0;n<NQ;n++) a[n] = angles[idx*NQ + n];
  float dtr[5];
#pragma unroll
  for (int r=0;r<5;r++){
    float s = 0.f;
#pragma unroll
    for (int n=0;n<NQ;n++) s += a[n]*W_x[r*NQ+n];
    dtr[r]=s;
  }
#pragma unroll
  for (int k=0;k<NQ;k++){
    float s=0.f;
#pragma unroll
    for (int n=0;n<NQ;n++) s += a[n]*W_x[(15+k)*NQ+n];
    g_C[idx*NQ+k]=s;
  }
#pragma unroll
  for (int n=0;n<NQ;n++){
    float s = b_dt[n];
#pragma unroll
    for (int r=0;r<5;r++) s += dtr[r]*W_dt[n*5+r];
    float sp = fmaxf(s, 0.f) + log1pf(expf(-fabsf(s)));
    g_dta[idx*NQ+n] = tanhf(sp)*PI_F;
  }
}

// complex shuffle gate on lane bit q, register-resident coefficients
__device__ __forceinline__ void shflCr(u64* v, const u64* Cq, int q){
  u64 csx=Cq[0], csy=Cq[1], cpx=Cq[2], cpy=Cq[3];
#pragma unroll
  for (int m=0;m<AMPS;m++){
    u64 p = __shfl_xor_sync(0xffffffffu, v[m], 1<<q);
    u64 P = fma2d(cpx, p, mul2d(csx, v[m]));
    u64 Q = fma2d(cpy, p, mul2d(csy, v[m]));
    v[m] = fixPQ(P, Q);
  }
}

// real (RY) shuffle gate on lane bit q
__device__ __forceinline__ void shflRp(u64* v, float c, float s, int q, int lane){
  float sp = ((lane >> q) & 1) ? s : -s;
  u64 c2 = pk2(c, c), sp2 = pk2(sp, sp);
#pragma unroll
  for (int m=0;m<AMPS;m++){
    u64 p = __shfl_xor_sync(0xffffffffu, v[m], 1<<q);
    v[m] = fma2d(sp2, p, mul2d(c2, v[m]));
  }
}

// complex register gate on m-bit bm (shared coefficients)
__device__ __forceinline__ void regCp(u64* v, const u64* G, int bm){
  u64 g0x=G[0],g0y=G[1],g1x=G[2],g1y=G[3],g2x=G[4],g2y=G[5],g3x=G[6],g3y=G[7];
#pragma unroll
  for (int m=0;m<AMPS;m++){
    if (m & bm) continue;
    int mh = m | bm;
    u64 lo = v[m], hi = v[mh];
    u64 P = fma2d(g1x, hi, mul2d(g0x, lo));
    u64 Q = fma2d(g1y, hi, mul2d(g0y, lo));
    v[m]  = fixPQ(P, Q);
    P = fma2d(g3x, hi, mul2d(g2x, lo));
    Q = fma2d(g3y, hi, mul2d(g2y, lo));
    v[mh] = fixPQ(P, Q);
  }
}

// real register gate on m-bit bm
__device__ __forceinline__ void regRp(u64* v, float c, float s, int bm){
  u64 c2 = pk2(c,c), s2 = pk2(s,s), ns2 = pk2(-s,-s);
#pragma unroll
  for (int m=0;m<AMPS;m++){
    if (m & bm) continue;
    int mh = m | bm;
    u64 lo = v[m], hi = v[mh];
    v[m]  = fma2d(ns2, hi, mul2d(c2, lo));
    v[mh] = fma2d(c2, hi, mul2d(s2, lo));
  }
}

// ---------------------------------------------------------------------------
// 256 threads, 4 amps/thread, state packed (re,im) per u64.
// L0 layout: amp a = tid*4+m; bits [1:0]=m (wires 8,9), [6:2]=lane (wires 3..7),
// [9:7]=warp (wires 0,1,2). L1 layout = bitswap(9<->1, 8<->0, 7<->2).
// Transpose exchanges carry cross-wire gates; chain gathers fused into the
// exchanges' store addresses. Complex shuffle-gate coefficients are hoisted
// into per-thread registers ONCE (lane-bit selection is thread-invariant).
// ---------------------------------------------------------------------------
__global__ __launch_bounds__(TPB, 1) void qmamba_main(
    const float* __restrict__ angles,
    const float* __restrict__ poly,
    const float* __restrict__ cparams,
    const float* __restrict__ Dg,
    float* __restrict__ out)
{
  __shared__ u64 bufA[NST], bufB[NST];
  __shared__ float2 Ug[20][4];
  __shared__ u64 Ugp[20][2][4];      // packed shuffle coeffs (staging)
  __shared__ u64 Urp[8][8];          // packed reg coeffs {0,1,8,9,10,11,18,19}
  __shared__ float Slo[32], Shi[32], Alo[32], Ahi[32];
  __shared__ float chs[NQ], shs[NQ], whs[NQ], fcs[NQ], fss[NQ];
  __shared__ float pcs[4], Dsh[NQ];
  __shared__ float zred[8][NQ];

  const int tid = threadIdx.x;
  const int lane = tid & 31;
  const int warp = tid >> 5;
  const int b = blockIdx.x;

  // ---- setup ---------------------------------------------------------------
  if (tid < 20) {
    int layer = tid/10, wire = tid%10;
    int k = (layer*NQ + wire)*3;
    float al = cparams[k], be = cparams[k+1], ga = cparams[k+2];
    float sa, ca, sb, cb, sg, cg;
    sincosf(0.5f*al, &sa, &ca);
    sincosf(0.5f*be, &sb, &cb);
    sincosf(0.5f*ga, &sg, &cg);
    float2 m00 = make_float2( cb*ca,  sb*sa);
    float2 m01 = make_float2(-sb*ca, -cb*sa);
    float2 m10 = make_float2( sb*ca, -cb*sa);
    float2 m11 = make_float2( cb*ca, -sb*sa);
    float2 e0 = make_float2(cg, -sg);
    float2 e1 = make_float2(cg,  sg);
    Ug[tid][0] = cmul(e0, m00);
    Ug[tid][1] = cmul(e0, m01);
    Ug[tid][2] = cmul(e1, m10);
    Ug[tid][3] = cmul(e1, m11);
  }
  if (tid < 4) pcs[tid] = poly[tid];
  float pA = 0.f, pC = 0.f;
  if (tid < NQ) {
    Dsh[tid] = Dg[tid];
    int bi = b*SQ*NQ + tid;
    pA = angles[bi]; pC = g_C[bi];
    float dta = g_dta[bi];
    chs[tid] = 1.f; shs[tid] = 0.f;     // h=0 at step 0
    whs[tid] = dta * (0.5f*PI_F);
    float s_, c_;
    __sincosf(0.5f*pA*dta, &s_, &c_);
    fcs[tid] = c_; fss[tid] = s_;
  }
  __syncthreads();

  // static packed shuffle-gate coefficients Ugp[g][bt][c] (staging)
  if (tid < 160) {
    int g = tid >> 3;
    int bt = (tid >> 2) & 1;
    int c = tid & 3;
    float2 cs = bt ? Ug[g][3] : Ug[g][0];
    float2 cp = bt ? Ug[g][2] : Ug[g][1];
    float val = (c==0) ? cs.x : (c==1) ? cs.y : (c==2) ? cp.x : cp.y;
    Ugp[g][bt][c] = pk2(val, val);
  }
  // static packed reg-gate coefficients for gates {0,1,8,9,10,11,18,19}
  if (tid < 64) {
    const int glist[8] = {0,1,8,9,10,11,18,19};
    int gi = tid >> 3;
    int c = (tid >> 1) & 3;
    int part = tid & 1;
    float2 gv = Ug[glist[gi]][c];
    float val = part ? gv.y : gv.x;
    Urp[gi][2*c+part] = pk2(val, val);
  }

  // per-thread static: QSVT gather powers + exchange index sets
  int rT1[AMPS], rT2[AMPS], rT3[AMPS], rT4[AMPS];
  int dstT[AMPS], dstG[AMPS];
#pragma unroll
  for (int m=0;m<AMPS;m++){
    int a = tid*AMPS + m;
    rT1[m] = gmap(a);
    rT2[m] = gmap(rT1[m]);
    rT3[m] = gmap(rT2[m]);
    rT4[m] = gmap(rT3[m]);
    int xp = bswap(a);
    int t1 = xp >> 2;
    dstT[m] = ((xp & 3) << 8) | (t1 ^ ((t1 >> 5) & 1));
    int xg = grayinv(xp);
    int tg = xg >> 2;
    dstG[m] = ((xg & 3) << 8) | (tg ^ ((tg >> 5) & 1));
  }
  const int ldb = tid ^ ((tid >> 5) & 1);   // own-slot swizzled load base
  __syncthreads();

  // ---- hoist complex shuffle-gate coefficients into registers --------------
  // CC order: [0..4]=gates 3..7 (lane bits 4..0), [5]=gate 2 (bit0),
  //           [6..10]=gates 13..17, [11]=gate 12 (bit0)
  u64 CC[12][4];
  {
    const int gl[12] = {3,4,5,6,7, 2, 13,14,15,16,17, 12};
    const int qb[12] = {4,3,2,1,0, 0, 4,3,2,1,0, 0};
#pragma unroll
    for (int i=0;i<12;i++){
      int bt = (lane >> qb[i]) & 1;
#pragma unroll
      for (int c=0;c<4;c++) CC[i][c] = Ugp[gl[i]][bt][c];
    }
  }

  u64 v[AMPS];

  // ---- sequential scan -----------------------------------------------------
#pragma unroll 1
  for (int s = 0; s < SQ; ++s) {
    // prefetch next-step per-wire inputs
    float nA=0.f, nD=0.f, nC=0.f;
    if (tid < NQ && s+1 < SQ) {
      int bn = (b*SQ + s + 1)*NQ + tid;
      nA = angles[bn]; nD = g_dta[bn]; nC = g_C[bn];
    }
    // per-step split tables over 5-bit halves
    if (tid < 64) {
      int j = tid & 31;
      bool hi = tid >= 32;
      float sm = 0.f, am = 1.f;
#pragma unroll
      for (int q=0;q<5;q++){
        int w = hi ? (4-q) : (9-q);
        int bit = (j>>q)&1;
        sm += bit ? whs[w] : -whs[w];
        am *= bit ? shs[w] : chs[w];
      }
      if (hi){ Shi[j]=sm; Ahi[j]=am; } else { Slo[j]=sm; Alo[j]=am; }
    }
    __syncthreads();

    // init in registers (L0): product state advanced through entire QSVT block
    {
      float p0=pcs[0], p1=pcs[1], p2=pcs[2], p3=pcs[3];
#pragma unroll
      for (int m=0;m<AMPS;m++){
        float phi = p3*(Shi[rT1[m]>>5] + Slo[rT1[m]&31])
                  + p2*(Shi[rT2[m]>>5] + Slo[rT2[m]&31])
                  + p1*(Shi[rT3[m]>>5] + Slo[rT3[m]&31])
                  + p0*(Shi[rT4[m]>>5] + Slo[rT4[m]&31]);
        float am = Ahi[rT4[m]>>5] * Alo[rT4[m]&31];
        float sp, cp; __sincosf(phi, &sp, &cp);
        v[m] = pk2(am*cp, am*sp);
      }
    }

    // ==== phase A (L0): layer-1 wires 3..7 (shfl), 8,9 (reg) ====
    shflCr(v, CC[0], 4);
    shflCr(v, CC[1], 3);
    shflCr(v, CC[2], 2);
    shflCr(v, CC[3], 1);
    shflCr(v, CC[4], 0);
    regCp(v, Urp[2], 2);   // gate 8
    regCp(v, Urp[3], 1);   // gate 9
    // T1: L0 -> L1
#pragma unroll
    for (int m=0;m<AMPS;m++) bufA[dstT[m]] = v[m];
    __syncthreads();
#pragma unroll
    for (int m=0;m<AMPS;m++) v[m] = bufA[(m<<8) | ldb];
    // ==== phase B (L1): layer-1 wires 0 (m1), 1 (m0), 2 (lane0) ====
    regCp(v, Urp[0], 2);   // gate 0
    regCp(v, Urp[1], 1);   // gate 1
    shflCr(v, CC[5], 0);
    // G1: chain gather + back to L0
#pragma unroll
    for (int m=0;m<AMPS;m++) bufB[dstG[m]] = v[m];
    __syncthreads();
#pragma unroll
    for (int m=0;m<AMPS;m++) v[m] = bufB[(m<<8) | ldb];

    // ==== phase C (L0): layer-2 wires 3..7, 8,9 ====
    shflCr(v, CC[6], 4);
    shflCr(v, CC[7], 3);
    shflCr(v, CC[8], 2);
    shflCr(v, CC[9], 1);
    shflCr(v, CC[10], 0);
    regCp(v, Urp[6], 2);   // gate 18
    regCp(v, Urp[7], 1);   // gate 19
    // T2: L0 -> L1
#pragma unroll
    for (int m=0;m<AMPS;m++) bufA[dstT[m]] = v[m];
    __syncthreads();
#pragma unroll
    for (int m=0;m<AMPS;m++) v[m] = bufA[(m<<8) | ldb];
    // ==== phase D (L1): layer-2 wires 0,1,2 ====
    regCp(v, Urp[4], 2);   // gate 10
    regCp(v, Urp[5], 1);   // gate 11
    shflCr(v, CC[11], 0);
    // G2: chain gather + back to L0
#pragma unroll
    for (int m=0;m<AMPS;m++) bufB[dstG[m]] = v[m];
    __syncthreads();
#pragma unroll
    for (int m=0;m<AMPS;m++) v[m] = bufB[(m<<8) | ldb];

    // ==== phase E (L0): final RY wires 3..7, 8,9 ====
    shflRp(v, fcs[3], fss[3], 4, lane);
    shflRp(v, fcs[4], fss[4], 3, lane);
    shflRp(v, fcs[5], fss[5], 2, lane);
    shflRp(v, fcs[6], fss[6], 1, lane);
    shflRp(v, fcs[7], fss[7], 0, lane);
    regRp(v, fcs[8], fss[8], 2);
    regRp(v, fcs[9], fss[9], 1);
    // T3: L0 -> L1
#pragma unroll
    for (int m=0;m<AMPS;m++) bufA[dstT[m]] = v[m];
    __syncthreads();
#pragma unroll
    for (int m=0;m<AMPS;m++) v[m] = bufA[(m<<8) | ldb];
    // ==== phase F (L1): final RY wires 0,1,2 ====
    regRp(v, fcs[0], fss[0], 2);
    regRp(v, fcs[1], fss[1], 1);
    shflRp(v, fcs[2], fss[2], 0, lane);

    // ======== measurement (L1 layout) ========
    float S=0.f, SbH=0.f, SbL=0.f;
#pragma unroll
    for (int m=0;m<AMPS;m++){
      float2 f = up2(v[m]);
      float pm = f.x*f.x + f.y*f.y;
      S += pm;
      if (m & 2) SbH += pm;   // wire 0
      if (m & 1) SbL += pm;   // wire 1
    }
#pragma unroll
    for (int off=16; off>0; off>>=1){
      SbH += __shfl_xor_sync(0xffffffffu, SbH, off);
      SbL += __shfl_xor_sync(0xffffffffu, SbL, off);
    }
    // Walsh-Hadamard on S over 5 lane bits
#pragma unroll
    for (int q=16; q>0; q>>=1){
      float t = __shfl_xor_sync(0xffffffffu, S, q);
      S = ((lane & q) ? (t - S) : (S + t));
    }
    if (lane == 0){
      zred[warp][8] = (warp&4) ? -S : S;   // amp bit9 = wire 8
      zred[warp][9] = (warp&2) ? -S : S;   // amp bit8 = wire 9
      zred[warp][7] = (warp&1) ? -S : S;   // amp bit7 = wire 7
      zred[warp][0] = S - 2.f*SbH;         // wire 0
      zred[warp][1] = S - 2.f*SbL;         // wire 1
    } else if (lane == 16) zred[warp][3] = S;  // amp bit6 = wire 3
    else if (lane == 8)  zred[warp][4] = S;    // wire 4
    else if (lane == 4)  zred[warp][5] = S;    // wire 5
    else if (lane == 2)  zred[warp][6] = S;    // wire 6
    else if (lane == 1)  zred[warp][2] = S;    // amp bit2 = wire 2
    __syncthreads();

    if (tid < NQ){
      float hn = zred[0][tid] + zred[1][tid] + zred[2][tid] + zred[3][tid]
               + zred[4][tid] + zred[5][tid] + zred[6][tid] + zred[7][tid];
      int bi = (b*SQ + s)*NQ + tid;
      out[bi] = pC*hn + Dsh[tid]*pA;
      if (s+1 < SQ){
        float s_, c_;
        __sincosf(0.5f*hn, &s_, &c_);
        chs[tid] = c_; shs[tid] = s_;
        whs[tid] = nD * (0.5f*PI_F);
        __sincosf(0.5f*nA*nD, &s_, &c_);
        fcs[tid] = c_; fss[tid] = s_;
        pA = nA; pC = nC;
      }
    }
    __syncthreads();
  }
}

// ---------------------------------------------------------------------------
extern "C" void kernel_launch(void* const* d_in, const int* in_sizes, int n_in,
                              void* d_out, int out_size)
{
  const float* angles  = (const float*)d_in[0];
  const float* W_x     = (const float*)d_in[1];
  const float* W_dt    = (const float*)d_in[2];
  const float* b_dt    = (const float*)d_in[3];
  const float* poly    = (const float*)d_in[4];
  const float* cparams = (const float*)d_in[5];
  const float* D       = (const float*)d_in[6];
  float* out = (float*)d_out;

  prep_kernel<<<(BQ*SQ + 255)/256, 256>>>(angles, W_x, W_dt, b_dt);
  qmamba_main<<<BQ, TPB>>>(angles, poly, cparams, D, out);
}